// round 2
// baseline (speedup 1.0000x reference)
#include <cuda_runtime.h>
#include <cstdint>

#define BATCH    8192
#define ENT_DIM  64
#define GRID_G   16
#define EMB_DIM  1024      // ENT_DIM * GRID_G
#define N_REL    5000
#define LN_EPS   1e-5f
#define NTHREADS 256
#define PER_THR  4         // EMB_DIM / NTHREADS

// Flag: 1 if proj_ids is int64 on device, 0 if int32.
__device__ int g_ids_is64;

__global__ void detect_ids_kernel(const void* __restrict__ ids) {
    // 64 threads check the first 64 entries interpreted as int64.
    // If the data is really int32, the int64 interpretation packs two random
    // ids (each in [0,5000)) into one 8-byte word -> value >= 2^32 almost
    // surely (fails only if the high int32 happens to be 0, p ~ 1/5000 each;
    // all-64 passing by chance is ~5000^-32).
    __shared__ int ok[64];
    const long long* p = (const long long*)ids;
    long long v = p[threadIdx.x];
    ok[threadIdx.x] = (v >= 0 && v < N_REL) ? 1 : 0;
    __syncthreads();
    if (threadIdx.x == 0) {
        int all = 1;
        #pragma unroll
        for (int i = 0; i < 64; i++) all &= ok[i];
        g_ids_is64 = all;
    }
}

__global__ __launch_bounds__(NTHREADS)
void proj_ln_kernel(const float* __restrict__ ent_emb,
                    const void*  __restrict__ proj_ids,
                    const float* __restrict__ rel_tran,
                    const float* __restrict__ rel_bias,
                    const float* __restrict__ ln_w,
                    const float* __restrict__ ln_b,
                    float* __restrict__ out)
{
    const int b = blockIdx.x;
    const int t = threadIdx.x;

    long long r;
    if (g_ids_is64) r = ((const long long*)proj_ids)[b];
    else            r = (long long)((const int*)proj_ids)[b];

    __shared__ float se[EMB_DIM];
    __shared__ float red_s[NTHREADS / 32];
    __shared__ float red_ss[NTHREADS / 32];
    __shared__ float s_mu, s_rstd;

    // Stage e row into smem (256 x float4 = 1024 floats), coalesced.
    {
        const float4* e4 = (const float4*)(ent_emb + (size_t)b * EMB_DIM);
        ((float4*)se)[t] = e4[t];
    }

    const float* T  = rel_tran + (size_t)r * (ENT_DIM * GRID_G * GRID_G);
    const float* Bm = rel_bias + (size_t)r * (ENT_DIM * GRID_G);

    // ---- Load phase: front-batch ALL global loads for max MLP ----
    // 16 x LDG.128 (T rows) + 4 x LDG.32 (bias), independent, no consumer
    // until the compute phase -> ptxas issues them back-to-back.
    float4 a[PER_THR][4];
    float  bias[PER_THR];
    #pragma unroll
    for (int k = 0; k < PER_THR; k++) {
        const int j = t + k * NTHREADS;       // output index in [0,1024)
        const float4* Trow = (const float4*)(T + (size_t)j * GRID_G);
        #pragma unroll
        for (int q = 0; q < 4; q++) a[k][q] = Trow[q];
        bias[k] = Bm[j];
    }
    __syncthreads();   // se ready (overlapped with the global loads above)

    // ---- Compute phase ----
    float x[PER_THR];
    float sum = 0.f, sumsq = 0.f;
    #pragma unroll
    for (int k = 0; k < PER_THR; k++) {
        const int j = t + k * NTHREADS;
        const int d = j >> 4;                 // ent_dim block
        const float4* ed = (const float4*)(se + d * GRID_G);
        float acc = bias[k];
        #pragma unroll
        for (int q = 0; q < 4; q++) {
            float4 av = a[k][q];
            float4 ev = ed[q];
            acc += av.x * ev.x + av.y * ev.y + av.z * ev.z + av.w * ev.w;
        }
        x[k] = acc;
        sum += acc;
        sumsq += acc * acc;
    }

    // Block reduction: warp shuffle then 8-warp smem combine.
    #pragma unroll
    for (int o = 16; o > 0; o >>= 1) {
        sum   += __shfl_xor_sync(0xFFFFFFFFu, sum,   o);
        sumsq += __shfl_xor_sync(0xFFFFFFFFu, sumsq, o);
    }
    const int lane = t & 31;
    const int wid  = t >> 5;
    if (lane == 0) { red_s[wid] = sum; red_ss[wid] = sumsq; }
    __syncthreads();
    if (t == 0) {
        float s = 0.f, ss = 0.f;
        #pragma unroll
        for (int i = 0; i < NTHREADS / 32; i++) { s += red_s[i]; ss += red_ss[i]; }
        const float inv_n = 1.0f / (float)EMB_DIM;
        const float mu = s * inv_n;
        const float var = ss * inv_n - mu * mu;
        s_mu = mu;
        s_rstd = rsqrtf(var + LN_EPS);
    }
    __syncthreads();
    const float mu   = s_mu;
    const float rstd = s_rstd;

    float* o = out + (size_t)b * EMB_DIM;
    #pragma unroll
    for (int k = 0; k < PER_THR; k++) {
        const int j = t + k * NTHREADS;
        o[j] = (x[k] - mu) * rstd * ln_w[j] + ln_b[j];
    }
}

extern "C" void kernel_launch(void* const* d_in, const int* in_sizes, int n_in,
                              void* d_out, int out_size) {
    const float* ent_emb  = (const float*)d_in[0];
    const void*  proj_ids = d_in[1];
    const float* rel_tran = (const float*)d_in[2];
    const float* rel_bias = (const float*)d_in[3];
    const float* ln_w     = (const float*)d_in[4];
    const float* ln_b     = (const float*)d_in[5];
    float* out = (float*)d_out;

    detect_ids_kernel<<<1, 64>>>(proj_ids);
    proj_ln_kernel<<<BATCH, NTHREADS>>>(ent_emb, proj_ids, rel_tran, rel_bias,
                                        ln_w, ln_b, out);
}